// round 16
// baseline (speedup 1.0000x reference)
#include <cuda_runtime.h>
#include <cuda_fp16.h>
#include <math.h>

// Problem constants
#define BB 4
#define NN 2048
#define CC 384
#define HH 8
#define HD 48
#define TT (BB * NN)          // 8192 tokens
#define SCALE 0.14433756729740645f       // 1/sqrt(48)
#define QMULT 0.20823444283700469f       // SCALE * log2(e)

// Scratch (static device globals — no runtime allocation)
__device__ float g_X[TT * CC];
__device__ __half g_Qh[TT * CC];   // head-major: [B][H][N][HD]
__device__ __half g_Kh[TT * CC];
__device__ __half g_Vh[TT * CC];

// ---------------------------------------------------------------------------
// MMA / async-copy helpers
// ---------------------------------------------------------------------------
__device__ __forceinline__ void ldsm_x4(unsigned int addr, unsigned int& r0,
                                        unsigned int& r1, unsigned int& r2, unsigned int& r3)
{
    asm volatile("ldmatrix.sync.aligned.m8n8.x4.shared.b16 {%0,%1,%2,%3}, [%4];"
                 : "=r"(r0), "=r"(r1), "=r"(r2), "=r"(r3) : "r"(addr));
}
__device__ __forceinline__ void ldsm_x4_t(unsigned int addr, unsigned int& r0,
                                          unsigned int& r1, unsigned int& r2, unsigned int& r3)
{
    asm volatile("ldmatrix.sync.aligned.m8n8.x4.trans.shared.b16 {%0,%1,%2,%3}, [%4];"
                 : "=r"(r0), "=r"(r1), "=r"(r2), "=r"(r3) : "r"(addr));
}
__device__ __forceinline__ void ldsm_x2_t(unsigned int addr, unsigned int& r0, unsigned int& r1)
{
    asm volatile("ldmatrix.sync.aligned.m8n8.x2.trans.shared.b16 {%0,%1}, [%2];"
                 : "=r"(r0), "=r"(r1) : "r"(addr));
}
__device__ __forceinline__ void mma16816(float* c, unsigned int a0, unsigned int a1,
                                         unsigned int a2, unsigned int a3,
                                         unsigned int b0, unsigned int b1)
{
    asm volatile("mma.sync.aligned.m16n8k16.row.col.f32.f16.f16.f32 "
                 "{%0,%1,%2,%3}, {%4,%5,%6,%7}, {%8,%9}, {%0,%1,%2,%3};"
                 : "+f"(c[0]), "+f"(c[1]), "+f"(c[2]), "+f"(c[3])
                 : "r"(a0), "r"(a1), "r"(a2), "r"(a3), "r"(b0), "r"(b1));
}
__device__ __forceinline__ unsigned int packh2(float x, float y)
{
    __half2 h = __floats2half2_rn(x, y);
    return *reinterpret_cast<unsigned int*>(&h);
}
__device__ __forceinline__ unsigned int h2ex2(unsigned int x)
{
    unsigned int r; asm("ex2.approx.f16x2 %0, %1;" : "=r"(r) : "r"(x)); return r;
}
__device__ __forceinline__ void cp16(unsigned int saddr, const void* gptr)
{
    asm volatile("cp.async.cg.shared.global [%0], [%1], 16;" :: "r"(saddr), "l"(gptr));
}
#define CP_COMMIT() asm volatile("cp.async.commit_group;")
#define CP_WAIT(n)  asm volatile("cp.async.wait_group %0;" :: "n"(n))

#define GS 40   // shared row stride in halfs (80B: conflict-free ldmatrix)

// ---------------------------------------------------------------------------
// fp16 GEMM mainloop, DOUBLE-BUFFERED smem (one barrier per k-iter).
// For GEMMs whose outputs round to fp16 anyway (Q/K/V projections).
// CTA tile 128x64, BK=32, 8 warps (4m x 2n).
// ---------------------------------------------------------------------------
#define ABUF (128 * GS)
#define WBUF (64 * GS)
#define BUFE (ABUF + WBUF)

__device__ __forceinline__ void sts_cvt_tile(__half* sm, int buf,
                                             const float4 ra[4], const float4 rw[2],
                                             int tid)
{
    __half* sa = sm + buf * BUFE;
    __half* sw = sa + ABUF;
#pragma unroll
    for (int p = 0; p < 4; p++) {
        int e = tid + p * 256;
        int r = e >> 3, c4 = (e & 7) * 4;
        float4 x = ra[p];
        __half2 h01 = __floats2half2_rn(x.x, x.y);
        __half2 h23 = __floats2half2_rn(x.z, x.w);
        uint2 ho;
        ho.x = *reinterpret_cast<unsigned int*>(&h01);
        ho.y = *reinterpret_cast<unsigned int*>(&h23);
        *(uint2*)&sa[r * GS + c4] = ho;
    }
#pragma unroll
    for (int p = 0; p < 2; p++) {
        int e = tid + p * 256;
        int r = e >> 3, c4 = (e & 7) * 4;
        float4 x = rw[p];
        __half2 h01 = __floats2half2_rn(x.x, x.y);
        __half2 h23 = __floats2half2_rn(x.z, x.w);
        uint2 ho;
        ho.x = *reinterpret_cast<unsigned int*>(&h01);
        ho.y = *reinterpret_cast<unsigned int*>(&h23);
        *(uint2*)&sw[r * GS + c4] = ho;
    }
}

__device__ __forceinline__ void gemm_mainloop_h(const float* __restrict__ A,
                                                const float* __restrict__ W,
                                                __half* sm,
                                                int row0, int col0,
                                                int tid, int lane, int wm, int wn,
                                                float acc[2][4][4])
{
#pragma unroll
    for (int mt = 0; mt < 2; mt++)
#pragma unroll
        for (int n8 = 0; n8 < 4; n8++)
#pragma unroll
            for (int j = 0; j < 4; j++) acc[mt][n8][j] = 0.f;

    unsigned int base = (unsigned int)__cvta_generic_to_shared(sm);
    int a_off = (wm * 32 + (lane & 15)) * GS + (lane >> 4) * 8;
    int w_off = (wn * 32 + (lane & 7) + ((lane >> 4) & 1) * 8) * GS + ((lane >> 3) & 1) * 8;

    float4 ra[4], rw[2];
#pragma unroll
    for (int p = 0; p < 4; p++) {
        int e = tid + p * 256;
        int r = e >> 3, c4 = (e & 7) * 4;
        ra[p] = *(const float4*)(A + (size_t)(row0 + r) * CC + c4);
    }
#pragma unroll
    for (int p = 0; p < 2; p++) {
        int e = tid + p * 256;
        int r = e >> 3, c4 = (e & 7) * 4;
        rw[p] = *(const float4*)(W + (size_t)(col0 + r) * CC + c4);
    }
    sts_cvt_tile(sm, 0, ra, rw, tid);
    __syncthreads();

    const int NK = CC / 32;   // 12
    for (int k = 0; k < NK; k++) {
        int cur = k & 1;
        if (k + 1 < NK) {
            int kc = (k + 1) * 32;
#pragma unroll
            for (int p = 0; p < 4; p++) {
                int e = tid + p * 256;
                int r = e >> 3, c4 = (e & 7) * 4;
                ra[p] = *(const float4*)(A + (size_t)(row0 + r) * CC + kc + c4);
            }
#pragma unroll
            for (int p = 0; p < 2; p++) {
                int e = tid + p * 256;
                int r = e >> 3, c4 = (e & 7) * 4;
                rw[p] = *(const float4*)(W + (size_t)(col0 + r) * CC + kc + c4);
            }
        }

        unsigned int a_b = base + (unsigned int)(cur * BUFE * 2);
        unsigned int w_b = a_b + (unsigned int)(ABUF * 2);
#pragma unroll
        for (int kt = 0; kt < 2; kt++) {
            unsigned int ah[2][4];
#pragma unroll
            for (int mt = 0; mt < 2; mt++) {
                unsigned int off = (unsigned int)((a_off + mt * 16 * GS + kt * 16) * 2);
                ldsm_x4(a_b + off, ah[mt][0], ah[mt][1], ah[mt][2], ah[mt][3]);
            }
#pragma unroll
            for (int nt = 0; nt < 2; nt++) {
                unsigned int off = (unsigned int)((w_off + nt * 16 * GS + kt * 16) * 2);
                unsigned int wh0, wh1, wh2, wh3;
                ldsm_x4(w_b + off, wh0, wh1, wh2, wh3);
#pragma unroll
                for (int mt = 0; mt < 2; mt++) {
                    mma16816(acc[mt][nt * 2 + 0], ah[mt][0], ah[mt][1], ah[mt][2], ah[mt][3], wh0, wh1);
                    mma16816(acc[mt][nt * 2 + 1], ah[mt][0], ah[mt][1], ah[mt][2], ah[mt][3], wh2, wh3);
                }
            }
        }

        if (k + 1 < NK) {
            sts_cvt_tile(sm, (k + 1) & 1, ra, rw, tid);
            __syncthreads();
        }
    }
}

// ---------------------------------------------------------------------------
// Split-fp16 mainloop (single-buffered; gates final rel_err) — for gemm_out.
// ---------------------------------------------------------------------------
struct GemmSmemFull {
    __half sAh[128 * GS];
    __half sWh[64 * GS];
    __half sAl[128 * GS];
    __half sWl[64 * GS];
};

__device__ __forceinline__ void gemm_mainloop_split(const float* __restrict__ A,
                                                    const float* __restrict__ W,
                                                    GemmSmemFull* sm,
                                                    int row0, int col0,
                                                    int tid, int lane, int wm, int wn,
                                                    float acc[2][4][4])
{
#pragma unroll
    for (int mt = 0; mt < 2; mt++)
#pragma unroll
        for (int n8 = 0; n8 < 4; n8++)
#pragma unroll
            for (int j = 0; j < 4; j++) acc[mt][n8][j] = 0.f;

    unsigned int ah_b = (unsigned int)__cvta_generic_to_shared(sm->sAh);
    unsigned int wh_b = (unsigned int)__cvta_generic_to_shared(sm->sWh);
    unsigned int al_b = (unsigned int)__cvta_generic_to_shared(sm->sAl);
    unsigned int wl_b = (unsigned int)__cvta_generic_to_shared(sm->sWl);

    int a_off = (wm * 32 + (lane & 15)) * GS + (lane >> 4) * 8;
    int w_off = (wn * 32 + (lane & 7) + ((lane >> 4) & 1) * 8) * GS + ((lane >> 3) & 1) * 8;

    float4 ra[4], rw[2];
#pragma unroll
    for (int p = 0; p < 4; p++) {
        int e = tid + p * 256;
        int r = e >> 3, c4 = (e & 7) * 4;
        ra[p] = *(const float4*)(A + (size_t)(row0 + r) * CC + c4);
    }
#pragma unroll
    for (int p = 0; p < 2; p++) {
        int e = tid + p * 256;
        int r = e >> 3, c4 = (e & 7) * 4;
        rw[p] = *(const float4*)(W + (size_t)(col0 + r) * CC + c4);
    }

    for (int k0 = 0; k0 < CC; k0 += 32) {
        __syncthreads();
#pragma unroll
        for (int p = 0; p < 4; p++) {
            int e = tid + p * 256;
            int r = e >> 3, c4 = (e & 7) * 4;
            float4 x = ra[p];
            __half2 h01 = __floats2half2_rn(x.x, x.y);
            __half2 h23 = __floats2half2_rn(x.z, x.w);
            float2 f01 = __half22float2(h01);
            float2 f23 = __half22float2(h23);
            __half2 l01 = __floats2half2_rn(x.x - f01.x, x.y - f01.y);
            __half2 l23 = __floats2half2_rn(x.z - f23.x, x.w - f23.y);
            uint2 ho, lo;
            ho.x = *reinterpret_cast<unsigned int*>(&h01);
            ho.y = *reinterpret_cast<unsigned int*>(&h23);
            lo.x = *reinterpret_cast<unsigned int*>(&l01);
            lo.y = *reinterpret_cast<unsigned int*>(&l23);
            *(uint2*)&sm->sAh[r * GS + c4] = ho;
            *(uint2*)&sm->sAl[r * GS + c4] = lo;
        }
#pragma unroll
        for (int p = 0; p < 2; p++) {
            int e = tid + p * 256;
            int r = e >> 3, c4 = (e & 7) * 4;
            float4 x = rw[p];
            __half2 h01 = __floats2half2_rn(x.x, x.y);
            __half2 h23 = __floats2half2_rn(x.z, x.w);
            float2 f01 = __half22float2(h01);
            float2 f23 = __half22float2(h23);
            __half2 l01 = __floats2half2_rn(x.x - f01.x, x.y - f01.y);
            __half2 l23 = __floats2half2_rn(x.z - f23.x, x.w - f23.y);
            uint2 ho, lo;
            ho.x = *reinterpret_cast<unsigned int*>(&h01);
            ho.y = *reinterpret_cast<unsigned int*>(&h23);
            lo.x = *reinterpret_cast<unsigned int*>(&l01);
            lo.y = *reinterpret_cast<unsigned int*>(&l23);
            *(uint2*)&sm->sWh[r * GS + c4] = ho;
            *(uint2*)&sm->sWl[r * GS + c4] = lo;
        }
        __syncthreads();

        if (k0 + 32 < CC) {
#pragma unroll
            for (int p = 0; p < 4; p++) {
                int e = tid + p * 256;
                int r = e >> 3, c4 = (e & 7) * 4;
                ra[p] = *(const float4*)(A + (size_t)(row0 + r) * CC + k0 + 32 + c4);
            }
#pragma unroll
            for (int p = 0; p < 2; p++) {
                int e = tid + p * 256;
                int r = e >> 3, c4 = (e & 7) * 4;
                rw[p] = *(const float4*)(W + (size_t)(col0 + r) * CC + k0 + 32 + c4);
            }
        }

#pragma unroll
        for (int kt = 0; kt < 2; kt++) {
            unsigned int ah[2][4], al[2][4];
#pragma unroll
            for (int mt = 0; mt < 2; mt++) {
                unsigned int off = (unsigned int)((a_off + mt * 16 * GS + kt * 16) * 2);
                ldsm_x4(ah_b + off, ah[mt][0], ah[mt][1], ah[mt][2], ah[mt][3]);
                ldsm_x4(al_b + off, al[mt][0], al[mt][1], al[mt][2], al[mt][3]);
            }
#pragma unroll
            for (int nt = 0; nt < 2; nt++) {
                unsigned int off = (unsigned int)((w_off + nt * 16 * GS + kt * 16) * 2);
                unsigned int wh0, wh1, wh2, wh3, wl0, wl1, wl2, wl3;
                ldsm_x4(wh_b + off, wh0, wh1, wh2, wh3);
                ldsm_x4(wl_b + off, wl0, wl1, wl2, wl3);
#pragma unroll
                for (int mt = 0; mt < 2; mt++) {
                    float* c0 = acc[mt][nt * 2 + 0];
                    float* c1 = acc[mt][nt * 2 + 1];
                    mma16816(c0, ah[mt][0], ah[mt][1], ah[mt][2], ah[mt][3], wh0, wh1);
                    mma16816(c1, ah[mt][0], ah[mt][1], ah[mt][2], ah[mt][3], wh2, wh3);
                    mma16816(c0, al[mt][0], al[mt][1], al[mt][2], al[mt][3], wh0, wh1);
                    mma16816(c1, al[mt][0], al[mt][1], al[mt][2], al[mt][3], wh2, wh3);
                    mma16816(c0, ah[mt][0], ah[mt][1], ah[mt][2], ah[mt][3], wl0, wl1);
                    mma16816(c1, ah[mt][0], ah[mt][1], ah[mt][2], ah[mt][3], wl2, wl3);
                }
            }
        }
    }
}

// ---------------------------------------------------------------------------
// QKV projection GEMM (fp16 DB mainloop) with FUSED RoPE + fp16 + head-major
// epilogue. blockIdx.z: 0 = Q (rope, *QMULT), 1 = K (rope), 2 = V.
// ---------------------------------------------------------------------------
__global__ __launch_bounds__(256) void gemm_qkv(const float* __restrict__ A0,
                                                const float* __restrict__ A1,
                                                const float* __restrict__ A2,
                                                const float* __restrict__ W0,
                                                const float* __restrict__ W1,
                                                const float* __restrict__ W2,
                                                const float* __restrict__ b0,
                                                const float* __restrict__ b1,
                                                const float* __restrict__ b2,
                                                const int* __restrict__ qpos,
                                                const int* __restrict__ kpos,
                                                __half* __restrict__ Qh,
                                                __half* __restrict__ Kh,
                                                __half* __restrict__ Vh)
{
    int z = blockIdx.z;
    const float* A    = z == 0 ? A0 : (z == 1 ? A1 : A2);
    const float* W    = z == 0 ? W0 : (z == 1 ? W1 : W2);
    const float* bias = z == 0 ? b0 : (z == 1 ? b1 : b2);
    const int* pos    = z == 0 ? qpos : kpos;
    __half* dst       = z == 0 ? Qh : (z == 1 ? Kh : Vh);
    float mult        = z == 0 ? QMULT : 1.0f;

    extern __shared__ char smraw[];
    __half* sm = reinterpret_cast<__half*>(smraw);
    int tid = threadIdx.x, lane = tid & 31, warp = tid >> 5;
    int wm = warp & 3, wn = warp >> 2;
    int row0 = blockIdx.y * 128;
    int col0 = blockIdx.x * 64;

    float acc[2][4][4];
    gemm_mainloop_h(A, W, sm, row0, col0, tid, lane, wm, wn, acc);

    const float LOG2_100 = 6.643856189774724f;
    int jj0 = (lane & 3) * 2;
    float inv0 = exp2f(-(float)jj0 * 0.125f * LOG2_100);
    float inv1 = exp2f(-(float)(jj0 + 1) * 0.125f * LOG2_100);

#pragma unroll
    for (int mt = 0; mt < 2; mt++) {
        int t0 = row0 + wm * 32 + mt * 16 + (lane >> 2);
#pragma unroll
        for (int p = 0; p < 2; p++) {
            int c0 = col0 + wn * 32 + p * 16;
            int hh = c0 / HD;
            int chunk = c0 % HD;
            int a = chunk / 16;

            float bx1a = bias[c0 + jj0],     bx1b = bias[c0 + jj0 + 1];
            float bx2a = bias[c0 + 8 + jj0], bx2b = bias[c0 + 8 + jj0 + 1];

#pragma unroll
            for (int rh = 0; rh < 2; rh++) {
                int t = t0 + rh * 8;
                float x1a = acc[mt][p * 2][rh * 2 + 0] + bx1a;
                float x1b = acc[mt][p * 2][rh * 2 + 1] + bx1b;
                float x2a = acc[mt][p * 2 + 1][rh * 2 + 0] + bx2a;
                float x2b = acc[mt][p * 2 + 1][rh * 2 + 1] + bx2b;

                if (z < 2) {
                    float pp = (float)pos[t * 3 + a];
                    float sa, ca, sb, cb;
                    sincosf(pp * inv0, &sa, &ca);
                    sincosf(pp * inv1, &sb, &cb);
                    float n1a = x1a * ca - x2a * sa;
                    float n2a = x2a * ca + x1a * sa;
                    float n1b = x1b * cb - x2b * sb;
                    float n2b = x2b * cb + x1b * sb;
                    x1a = n1a; x2a = n2a; x1b = n1b; x2b = n2b;
                }

                int bb = t / NN, nn = t % NN;
                __half* d = dst + ((size_t)(bb * HH + hh) * NN + nn) * HD + chunk + jj0;
                *(unsigned int*)d       = packh2(x1a * mult, x1b * mult);
                *(unsigned int*)(d + 8) = packh2(x2a * mult, x2b * mult);
            }
        }
    }
}

// ---------------------------------------------------------------------------
// Output projection GEMM (split-fp16; fp32 epilogue to d_out).
// ---------------------------------------------------------------------------
__global__ __launch_bounds__(256) void gemm_out(const float* __restrict__ A,
                                                const float* __restrict__ W,
                                                const float* __restrict__ bias,
                                                float* __restrict__ out)
{
    extern __shared__ char smraw[];
    GemmSmemFull* sm = reinterpret_cast<GemmSmemFull*>(smraw);
    int tid = threadIdx.x, lane = tid & 31, warp = tid >> 5;
    int wm = warp & 3, wn = warp >> 2;
    int row0 = blockIdx.y * 128;
    int col0 = blockIdx.x * 64;

    float acc[2][4][4];
    gemm_mainloop_split(A, W, sm, row0, col0, tid, lane, wm, wn, acc);

#pragma unroll
    for (int mt = 0; mt < 2; mt++) {
        int r = row0 + wm * 32 + mt * 16 + (lane >> 2);
#pragma unroll
        for (int n8 = 0; n8 < 4; n8++) {
            int c = col0 + wn * 32 + n8 * 8 + (lane & 3) * 2;
            float bx = bias[c], by = bias[c + 1];
            float2 f0, f1;
            f0.x = acc[mt][n8][0] + bx; f0.y = acc[mt][n8][1] + by;
            f1.x = acc[mt][n8][2] + bx; f1.y = acc[mt][n8][3] + by;
            *(float2*)&out[(size_t)r * CC + c] = f0;
            *(float2*)&out[(size_t)(r + 8) * CC + c] = f1;
        }
    }
}

// ---------------------------------------------------------------------------
// Tensor-core flash attention: 8 warps (256 threads), warp = 16 query rows,
// QT=128. Two warps per SMSP so MMA/softmax/LDS of different warps overlap.
// 64-key tiles double-buffered via cp.async; exp2-domain softmax with
// ex2.approx.f16x2; tensor-core denominator (ones-column in Vs); per-row
// max frozen after tile 0.
// ---------------------------------------------------------------------------
#define ATS 56
#define QT 128

__global__ __launch_bounds__(256) void attn_mma(const __half* __restrict__ Qh,
                                                const __half* __restrict__ Kh,
                                                const __half* __restrict__ Vh,
                                                float* __restrict__ X)
{
    __shared__ __half Qs[QT * ATS];
    __shared__ __half Ks[2][64 * ATS];
    __shared__ __half Vs[2][64 * ATS];

    int tid = threadIdx.x, lane = tid & 31, w = tid >> 5;
    int b = blockIdx.z, h = blockIdx.y;
    const size_t hb = ((size_t)(b * HH + h)) * NN * HD;
    int q0 = blockIdx.x * QT;

    unsigned int qs_base = (unsigned int)__cvta_generic_to_shared(Qs);
    unsigned int ks_base = (unsigned int)__cvta_generic_to_shared(&Ks[0][0]);
    unsigned int vs_base = (unsigned int)__cvta_generic_to_shared(&Vs[0][0]);
    const unsigned int BUFB = 64 * ATS * 2;

    if (tid < 64) {
        uint4 ones = {0x00003C00u, 0u, 0u, 0u};
        *(uint4*)&Vs[0][tid * ATS + 48] = ones;
        *(uint4*)&Vs[1][tid * ATS + 48] = ones;
    }

    for (int e = tid; e < QT * 6; e += 256) {
        int r = e / 6, c = e % 6;
        *(uint4*)&Qs[r * ATS + c * 8] = *(const uint4*)(Qh + hb + (size_t)(q0 + r) * HD + c * 8);
    }

    // Per-thread prefetch coordinates: 384 uint4 over 256 threads (p=1 only for tid<128)
    size_t gofs[2];
    unsigned int sofs[2];
    bool pv[2];
#pragma unroll
    for (int p = 0; p < 2; p++) {
        int e = tid + p * 256;
        pv[p] = (e < 384);
        int r = (e < 384 ? e : 0) / 6, c = (e < 384 ? e : 0) % 6;
        gofs[p] = (size_t)r * HD + c * 8;
        sofs[p] = (unsigned int)((r * ATS + c * 8) * 2);
    }

#pragma unroll
    for (int p = 0; p < 2; p++) if (pv[p]) {
        cp16(ks_base + sofs[p], Kh + hb + gofs[p]);
        cp16(vs_base + sofs[p], Vh + hb + gofs[p]);
    }
    CP_COMMIT();
    __syncthreads();

    // Q A-fragments: one m16 tile per warp (16 rows)
    unsigned int qa[3][4];
    {
        int arow = w * 16 + (lane & 15);
        int acol = (lane >> 4) * 8;
#pragma unroll
        for (int k = 0; k < 3; k++) {
            unsigned int addr = qs_base + (unsigned int)((arow * ATS + k * 16 + acol) * 2);
            ldsm_x4(addr, qa[k][0], qa[k][1], qa[k][2], qa[k][3]);
        }
    }

    float o[6][4];
    float ol[4];
    float m0f = 0.f, m1f = 0.f;
#pragma unroll
    for (int j = 0; j < 4; j++) ol[j] = 0.f;
#pragma unroll
    for (int n = 0; n < 6; n++)
#pragma unroll
        for (int j = 0; j < 4; j++) o[n][j] = 0.f;

    int kb_off = ((lane & 7) + ((lane >> 4) & 1) * 8) * ATS + ((lane >> 3) & 1) * 8;
    int vb_off = ((lane & 7) + ((lane >> 3) & 1) * 8) * ATS + ((lane >> 4) & 1) * 8;
    int vl_off = (lane & 15) * ATS + 48;

    const int NT = NN / 64;
    for (int kt = 0; kt < NT; kt++) {
        if (kt + 1 < NT) {
            unsigned int bo = ((kt + 1) & 1) * BUFB;
            size_t gb = hb + (size_t)(kt + 1) * 64 * HD;
#pragma unroll
            for (int p = 0; p < 2; p++) if (pv[p]) {
                cp16(ks_base + bo + sofs[p], Kh + gb + gofs[p]);
                cp16(vs_base + bo + sofs[p], Vh + gb + gofs[p]);
            }
            CP_COMMIT();
            CP_WAIT(1);
        } else {
            CP_WAIT(0);
        }
        __syncthreads();

        unsigned int bo = (kt & 1) * BUFB;

        // S = Q K^T (log2-domain scores)
        float s[8][4];
#pragma unroll
        for (int n = 0; n < 8; n++)
#pragma unroll
            for (int j = 0; j < 4; j++) s[n][j] = 0.f;

#pragma unroll
        for (int np = 0; np < 4; np++) {
#pragma unroll
            for (int k = 0; k < 3; k++) {
                unsigned int addr = ks_base + bo +
                    (unsigned int)(((np * 16) * ATS + k * 16 + kb_off) * 2);
                unsigned int b0, b1, b2, b3;
                ldsm_x4(addr, b0, b1, b2, b3);
                mma16816(s[2 * np],     qa[k][0], qa[k][1], qa[k][2], qa[k][3], b0, b1);
                mma16816(s[2 * np + 1], qa[k][0], qa[k][1], qa[k][2], qa[k][3], b2, b3);
            }
        }

        // Freeze per-row max from tile 0 (softmax m-invariant; fp16 range 2^16
        // covers the worst tile0-vs-global max gap with 3x log-margin).
        if (kt == 0) {
            float t0 = s[0][0], t1 = s[0][2];
#pragma unroll
            for (int n = 0; n < 8; n++) {
                t0 = fmaxf(t0, fmaxf(s[n][0], s[n][1]));
                t1 = fmaxf(t1, fmaxf(s[n][2], s[n][3]));
            }
            t0 = fmaxf(t0, __shfl_xor_sync(0xffffffffu, t0, 1));
            t0 = fmaxf(t0, __shfl_xor_sync(0xffffffffu, t0, 2));
            t1 = fmaxf(t1, __shfl_xor_sync(0xffffffffu, t1, 1));
            t1 = fmaxf(t1, __shfl_xor_sync(0xffffffffu, t1, 2));
            m0f = t0; m1f = t1;
        }

        // P = 2^(s - m) as f16x2; MMA into O and (ones-column) denominator.
#pragma unroll
        for (int k4 = 0; k4 < 4; k4++) {
            unsigned int a0 = h2ex2(packh2(s[2 * k4][0] - m0f,     s[2 * k4][1] - m0f));
            unsigned int a1 = h2ex2(packh2(s[2 * k4][2] - m1f,     s[2 * k4][3] - m1f));
            unsigned int a2 = h2ex2(packh2(s[2 * k4 + 1][0] - m0f, s[2 * k4 + 1][1] - m0f));
            unsigned int a3 = h2ex2(packh2(s[2 * k4 + 1][2] - m1f, s[2 * k4 + 1][3] - m1f));
#pragma unroll
            for (int np = 0; np < 3; np++) {
                unsigned int addr = vs_base + bo +
                    (unsigned int)(((k4 * 16) * ATS + np * 16 + vb_off) * 2);
                unsigned int b0, b1, b2, b3;
                ldsm_x4_t(addr, b0, b1, b2, b3);
                mma16816(o[2 * np],     a0, a1, a2, a3, b0, b1);
                mma16816(o[2 * np + 1], a0, a1, a2, a3, b2, b3);
            }
            {
                unsigned int laddr = vs_base + bo +
                    (unsigned int)(((k4 * 16) * ATS + vl_off) * 2);
                unsigned int b0, b1;
                ldsm_x2_t(laddr, b0, b1);
                mma16816(ol, a0, a1, a2, a3, b0, b1);
            }
        }
        __syncthreads();
    }

    // Final normalize + write. l lives in quad-lane 0 (col 48).
    {
        float l0 = __shfl_sync(0xffffffffu, ol[0], lane & ~3);
        float l1 = __shfl_sync(0xffffffffu, ol[2], lane & ~3);
        float i0 = 1.f / l0, i1 = 1.f / l1;

        int r0 = q0 + w * 16 + (lane >> 2);
        int cbase = h * HD + (lane & 3) * 2;
#pragma unroll
        for (int n = 0; n < 6; n++) {
            float2 f0; f0.x = o[n][0] * i0; f0.y = o[n][1] * i0;
            float2 f1; f1.x = o[n][2] * i1; f1.y = o[n][3] * i1;
            *(float2*)&X[(size_t)(b * NN + r0) * CC + cbase + n * 8] = f0;
            *(float2*)&X[(size_t)(b * NN + r0 + 8) * CC + cbase + n * 8] = f1;
        }
    }
}

// ---------------------------------------------------------------------------
// Launch
// ---------------------------------------------------------------------------
extern "C" void kernel_launch(void* const* d_in, const int* in_sizes, int n_in,
                              void* d_out, int out_size)
{
    const float* query = (const float*)d_in[0];
    const float* key   = (const float*)d_in[1];
    const float* value = (const float*)d_in[2];
    const float* Wq = (const float*)d_in[3];
    const float* bq = (const float*)d_in[4];
    const float* Wk = (const float*)d_in[5];
    const float* bk = (const float*)d_in[6];
    const float* Wv = (const float*)d_in[7];
    const float* bv = (const float*)d_in[8];
    const float* Wo = (const float*)d_in[9];
    const float* bo = (const float*)d_in[10];
    const int* qpos = (const int*)d_in[11];
    const int* kpos = (const int*)d_in[12];
    float* out = (float*)d_out;

    float* pX;
    __half *pQh, *pKh, *pVh;
    cudaGetSymbolAddress((void**)&pX, g_X);
    cudaGetSymbolAddress((void**)&pQh, g_Qh);
    cudaGetSymbolAddress((void**)&pKh, g_Kh);
    cudaGetSymbolAddress((void**)&pVh, g_Vh);

    // Ask for max shared-memory carveout so 2 CTAs can co-reside (idempotent,
    // cheap; errors ignored — attribute setting, not allocation).
    cudaFuncSetAttribute(gemm_qkv, cudaFuncAttributePreferredSharedMemoryCarveout, 100);
    cudaFuncSetAttribute(gemm_out, cudaFuncAttributePreferredSharedMemoryCarveout, 100);
    cudaFuncSetAttribute(attn_mma, cudaFuncAttributePreferredSharedMemoryCarveout, 100);

    const int smem_db   = 2 * BUFE * 2;                // 30720 B (double-buffered fp16)
    const int smem_full = 2 * (128 + 64) * GS * 2;     // 30720 B (split, single-buffered)

    dim3 g3(CC / 64, TT / 128, 3);
    gemm_qkv<<<g3, 256, smem_db>>>(query, key, value,
                                   Wq, Wk, Wv,
                                   bq, bk, bv,
                                   qpos, kpos,
                                   pQh, pKh, pVh);

    attn_mma<<<dim3(NN / QT, HH, BB), 256>>>(pQh, pKh, pVh, pX);

    dim3 g1(CC / 64, TT / 128);
    gemm_out<<<g1, 256, smem_full>>>(pX, Wo, bo, out);
}

// round 17
// speedup vs baseline: 1.1496x; 1.1496x over previous
#include <cuda_runtime.h>
#include <cuda_fp16.h>
#include <math.h>

// Problem constants
#define BB 4
#define NN 2048
#define CC 384
#define HH 8
#define HD 48
#define TT (BB * NN)          // 8192 tokens
#define SCALE 0.14433756729740645f       // 1/sqrt(48)
#define QMULT 0.20823444283700469f       // SCALE * log2(e)

// Scratch (static device globals — no runtime allocation)
__device__ float g_X[TT * CC];
__device__ __half g_Qh[TT * CC];   // head-major: [B][H][N][HD]
__device__ __half g_Kh[TT * CC];
__device__ __half g_Vh[TT * CC];
__device__ __half g_Ih[3 * TT * CC];   // fp16 copies of query|key|value
__device__ __half g_Wh[3 * CC * CC];   // fp16 copies of Wq|Wk|Wv

// ---------------------------------------------------------------------------
// MMA / async-copy helpers
// ---------------------------------------------------------------------------
__device__ __forceinline__ void ldsm_x4(unsigned int addr, unsigned int& r0,
                                        unsigned int& r1, unsigned int& r2, unsigned int& r3)
{
    asm volatile("ldmatrix.sync.aligned.m8n8.x4.shared.b16 {%0,%1,%2,%3}, [%4];"
                 : "=r"(r0), "=r"(r1), "=r"(r2), "=r"(r3) : "r"(addr));
}
__device__ __forceinline__ void ldsm_x4_t(unsigned int addr, unsigned int& r0,
                                          unsigned int& r1, unsigned int& r2, unsigned int& r3)
{
    asm volatile("ldmatrix.sync.aligned.m8n8.x4.trans.shared.b16 {%0,%1,%2,%3}, [%4];"
                 : "=r"(r0), "=r"(r1), "=r"(r2), "=r"(r3) : "r"(addr));
}
__device__ __forceinline__ void ldsm_x2_t(unsigned int addr, unsigned int& r0, unsigned int& r1)
{
    asm volatile("ldmatrix.sync.aligned.m8n8.x2.trans.shared.b16 {%0,%1}, [%2];"
                 : "=r"(r0), "=r"(r1) : "r"(addr));
}
__device__ __forceinline__ void mma16816(float* c, unsigned int a0, unsigned int a1,
                                         unsigned int a2, unsigned int a3,
                                         unsigned int b0, unsigned int b1)
{
    asm volatile("mma.sync.aligned.m16n8k16.row.col.f32.f16.f16.f32 "
                 "{%0,%1,%2,%3}, {%4,%5,%6,%7}, {%8,%9}, {%0,%1,%2,%3};"
                 : "+f"(c[0]), "+f"(c[1]), "+f"(c[2]), "+f"(c[3])
                 : "r"(a0), "r"(a1), "r"(a2), "r"(a3), "r"(b0), "r"(b1));
}
__device__ __forceinline__ unsigned int packh2(float x, float y)
{
    __half2 h = __floats2half2_rn(x, y);
    return *reinterpret_cast<unsigned int*>(&h);
}
__device__ __forceinline__ unsigned int h2ex2(unsigned int x)
{
    unsigned int r; asm("ex2.approx.f16x2 %0, %1;" : "=r"(r) : "r"(x)); return r;
}
__device__ __forceinline__ void cp16(unsigned int saddr, const void* gptr)
{
    asm volatile("cp.async.cg.shared.global [%0], [%1], 16;" :: "r"(saddr), "l"(gptr));
}
#define CP_COMMIT() asm volatile("cp.async.commit_group;")
#define CP_WAIT(n)  asm volatile("cp.async.wait_group %0;" :: "n"(n))

#define GS 40   // shared row stride in halfs (80B: conflict-free ldmatrix)
#define ABUF (128 * GS)
#define WBUF (64 * GS)
#define BUFE (ABUF + WBUF)

// ---------------------------------------------------------------------------
// Pre-pass: fp32 -> fp16 conversion of the three QKV inputs and weights.
// One thread handles 8 elements (float4 x2 -> uint4).
// ---------------------------------------------------------------------------
__global__ void cvt_in(const float* __restrict__ q, const float* __restrict__ k,
                       const float* __restrict__ v,
                       const float* __restrict__ wq, const float* __restrict__ wk,
                       const float* __restrict__ wv,
                       __half* __restrict__ Ih, __half* __restrict__ Wh)
{
    const int NI = TT * CC / 8;   // 393216 per input matrix
    const int NW = CC * CC / 8;   // 18432 per weight matrix
    int idx = blockIdx.x * blockDim.x + threadIdx.x;

    const float* src;
    __half* dst;
    int off;
    if (idx < 3 * NI) {
        int m = idx / NI, r = idx - m * NI;
        src = m == 0 ? q : (m == 1 ? k : v);
        dst = Ih + (size_t)m * (TT * CC);
        off = r;
    } else if (idx < 3 * NI + 3 * NW) {
        int t = idx - 3 * NI;
        int m = t / NW, r = t - m * NW;
        src = m == 0 ? wq : (m == 1 ? wk : wv);
        dst = Wh + (size_t)m * (CC * CC);
        off = r;
    } else {
        return;
    }

    float4 x0 = ((const float4*)src)[off * 2];
    float4 x1 = ((const float4*)src)[off * 2 + 1];
    __half2 h0 = __floats2half2_rn(x0.x, x0.y);
    __half2 h1 = __floats2half2_rn(x0.z, x0.w);
    __half2 h2 = __floats2half2_rn(x1.x, x1.y);
    __half2 h3 = __floats2half2_rn(x1.z, x1.w);
    uint4 o;
    o.x = *reinterpret_cast<unsigned int*>(&h0);
    o.y = *reinterpret_cast<unsigned int*>(&h1);
    o.z = *reinterpret_cast<unsigned int*>(&h2);
    o.w = *reinterpret_cast<unsigned int*>(&h3);
    ((uint4*)dst)[off] = o;
}

// ---------------------------------------------------------------------------
// fp16-input GEMM mainloop with cp.async DOUBLE-BUFFERED staging.
// CTA tile 128x64, BK=32, 8 warps (4m x 2n).
// ---------------------------------------------------------------------------
__device__ __forceinline__ void gemm_mainloop_h16(const __half* __restrict__ A,
                                                  const __half* __restrict__ W,
                                                  __half* sm,
                                                  int row0, int col0,
                                                  int tid, int lane, int wm, int wn,
                                                  float acc[2][4][4])
{
#pragma unroll
    for (int mt = 0; mt < 2; mt++)
#pragma unroll
        for (int n8 = 0; n8 < 4; n8++)
#pragma unroll
            for (int j = 0; j < 4; j++) acc[mt][n8][j] = 0.f;

    unsigned int base = (unsigned int)__cvta_generic_to_shared(sm);
    int a_off = (wm * 32 + (lane & 15)) * GS + (lane >> 4) * 8;
    int w_off = (wn * 32 + (lane & 7) + ((lane >> 4) & 1) * 8) * GS + ((lane >> 3) & 1) * 8;

    // Per-thread cp.async coordinates (3 transfers of 16B each):
    // entries 0..511 stage A (128 rows x 4 chunks), 512..767 stage W.
    unsigned int so[3];
    const __half* gp[3];
#pragma unroll
    for (int p = 0; p < 3; p++) {
        int e = tid + p * 256;
        if (e < 512) {
            int r = e >> 2, c8 = e & 3;
            so[p] = (unsigned int)((r * GS + c8 * 8) * 2);
            gp[p] = A + (size_t)(row0 + r) * CC + c8 * 8;
        } else {
            int e2 = e - 512;
            int r = e2 >> 2, c8 = e2 & 3;
            so[p] = (unsigned int)((ABUF + r * GS + c8 * 8) * 2);
            gp[p] = W + (size_t)(col0 + r) * CC + c8 * 8;
        }
    }

    // Prologue: stage k-tile 0 into buffer 0
#pragma unroll
    for (int p = 0; p < 3; p++) cp16(base + so[p], gp[p]);
    CP_COMMIT();

    const int NK = CC / 32;   // 12
    for (int k = 0; k < NK; k++) {
        if (k + 1 < NK) {
            unsigned int bo = (unsigned int)(((k + 1) & 1) * BUFE * 2);
            int kc = (k + 1) * 32;
#pragma unroll
            for (int p = 0; p < 3; p++) cp16(base + bo + so[p], gp[p] + kc);
            CP_COMMIT();
            CP_WAIT(1);
        } else {
            CP_WAIT(0);
        }
        __syncthreads();

        unsigned int a_b = base + (unsigned int)((k & 1) * BUFE * 2);
        unsigned int w_b = a_b + (unsigned int)(ABUF * 2);
#pragma unroll
        for (int kt = 0; kt < 2; kt++) {
            unsigned int ah[2][4];
#pragma unroll
            for (int mt = 0; mt < 2; mt++) {
                unsigned int off = (unsigned int)((a_off + mt * 16 * GS + kt * 16) * 2);
                ldsm_x4(a_b + off, ah[mt][0], ah[mt][1], ah[mt][2], ah[mt][3]);
            }
#pragma unroll
            for (int nt = 0; nt < 2; nt++) {
                unsigned int off = (unsigned int)((w_off + nt * 16 * GS + kt * 16) * 2);
                unsigned int wh0, wh1, wh2, wh3;
                ldsm_x4(w_b + off, wh0, wh1, wh2, wh3);
#pragma unroll
                for (int mt = 0; mt < 2; mt++) {
                    mma16816(acc[mt][nt * 2 + 0], ah[mt][0], ah[mt][1], ah[mt][2], ah[mt][3], wh0, wh1);
                    mma16816(acc[mt][nt * 2 + 1], ah[mt][0], ah[mt][1], ah[mt][2], ah[mt][3], wh2, wh3);
                }
            }
        }
        __syncthreads();
    }
}

// ---------------------------------------------------------------------------
// Split-fp16 mainloop (single-buffered; gates final rel_err) — for gemm_out.
// ---------------------------------------------------------------------------
struct GemmSmemFull {
    __half sAh[128 * GS];
    __half sWh[64 * GS];
    __half sAl[128 * GS];
    __half sWl[64 * GS];
};

__device__ __forceinline__ void gemm_mainloop_split(const float* __restrict__ A,
                                                    const float* __restrict__ W,
                                                    GemmSmemFull* sm,
                                                    int row0, int col0,
                                                    int tid, int lane, int wm, int wn,
                                                    float acc[2][4][4])
{
#pragma unroll
    for (int mt = 0; mt < 2; mt++)
#pragma unroll
        for (int n8 = 0; n8 < 4; n8++)
#pragma unroll
            for (int j = 0; j < 4; j++) acc[mt][n8][j] = 0.f;

    unsigned int ah_b = (unsigned int)__cvta_generic_to_shared(sm->sAh);
    unsigned int wh_b = (unsigned int)__cvta_generic_to_shared(sm->sWh);
    unsigned int al_b = (unsigned int)__cvta_generic_to_shared(sm->sAl);
    unsigned int wl_b = (unsigned int)__cvta_generic_to_shared(sm->sWl);

    int a_off = (wm * 32 + (lane & 15)) * GS + (lane >> 4) * 8;
    int w_off = (wn * 32 + (lane & 7) + ((lane >> 4) & 1) * 8) * GS + ((lane >> 3) & 1) * 8;

    float4 ra[4], rw[2];
#pragma unroll
    for (int p = 0; p < 4; p++) {
        int e = tid + p * 256;
        int r = e >> 3, c4 = (e & 7) * 4;
        ra[p] = *(const float4*)(A + (size_t)(row0 + r) * CC + c4);
    }
#pragma unroll
    for (int p = 0; p < 2; p++) {
        int e = tid + p * 256;
        int r = e >> 3, c4 = (e & 7) * 4;
        rw[p] = *(const float4*)(W + (size_t)(col0 + r) * CC + c4);
    }

    for (int k0 = 0; k0 < CC; k0 += 32) {
        __syncthreads();
#pragma unroll
        for (int p = 0; p < 4; p++) {
            int e = tid + p * 256;
            int r = e >> 3, c4 = (e & 7) * 4;
            float4 x = ra[p];
            __half2 h01 = __floats2half2_rn(x.x, x.y);
            __half2 h23 = __floats2half2_rn(x.z, x.w);
            float2 f01 = __half22float2(h01);
            float2 f23 = __half22float2(h23);
            __half2 l01 = __floats2half2_rn(x.x - f01.x, x.y - f01.y);
            __half2 l23 = __floats2half2_rn(x.z - f23.x, x.w - f23.y);
            uint2 ho, lo;
            ho.x = *reinterpret_cast<unsigned int*>(&h01);
            ho.y = *reinterpret_cast<unsigned int*>(&h23);
            lo.x = *reinterpret_cast<unsigned int*>(&l01);
            lo.y = *reinterpret_cast<unsigned int*>(&l23);
            *(uint2*)&sm->sAh[r * GS + c4] = ho;
            *(uint2*)&sm->sAl[r * GS + c4] = lo;
        }
#pragma unroll
        for (int p = 0; p < 2; p++) {
            int e = tid + p * 256;
            int r = e >> 3, c4 = (e & 7) * 4;
            float4 x = rw[p];
            __half2 h01 = __floats2half2_rn(x.x, x.y);
            __half2 h23 = __floats2half2_rn(x.z, x.w);
            float2 f01 = __half22float2(h01);
            float2 f23 = __half22float2(h23);
            __half2 l01 = __floats2half2_rn(x.x - f01.x, x.y - f01.y);
            __half2 l23 = __floats2half2_rn(x.z - f23.x, x.w - f23.y);
            uint2 ho, lo;
            ho.x = *reinterpret_cast<unsigned int*>(&h01);
            ho.y = *reinterpret_cast<unsigned int*>(&h23);
            lo.x = *reinterpret_cast<unsigned int*>(&l01);
            lo.y = *reinterpret_cast<unsigned int*>(&l23);
            *(uint2*)&sm->sWh[r * GS + c4] = ho;
            *(uint2*)&sm->sWl[r * GS + c4] = lo;
        }
        __syncthreads();

        if (k0 + 32 < CC) {
#pragma unroll
            for (int p = 0; p < 4; p++) {
                int e = tid + p * 256;
                int r = e >> 3, c4 = (e & 7) * 4;
                ra[p] = *(const float4*)(A + (size_t)(row0 + r) * CC + k0 + 32 + c4);
            }
#pragma unroll
            for (int p = 0; p < 2; p++) {
                int e = tid + p * 256;
                int r = e >> 3, c4 = (e & 7) * 4;
                rw[p] = *(const float4*)(W + (size_t)(col0 + r) * CC + k0 + 32 + c4);
            }
        }

#pragma unroll
        for (int kt = 0; kt < 2; kt++) {
            unsigned int ah[2][4], al[2][4];
#pragma unroll
            for (int mt = 0; mt < 2; mt++) {
                unsigned int off = (unsigned int)((a_off + mt * 16 * GS + kt * 16) * 2);
                ldsm_x4(ah_b + off, ah[mt][0], ah[mt][1], ah[mt][2], ah[mt][3]);
                ldsm_x4(al_b + off, al[mt][0], al[mt][1], al[mt][2], al[mt][3]);
            }
#pragma unroll
            for (int nt = 0; nt < 2; nt++) {
                unsigned int off = (unsigned int)((w_off + nt * 16 * GS + kt * 16) * 2);
                unsigned int wh0, wh1, wh2, wh3, wl0, wl1, wl2, wl3;
                ldsm_x4(wh_b + off, wh0, wh1, wh2, wh3);
                ldsm_x4(wl_b + off, wl0, wl1, wl2, wl3);
#pragma unroll
                for (int mt = 0; mt < 2; mt++) {
                    float* c0 = acc[mt][nt * 2 + 0];
                    float* c1 = acc[mt][nt * 2 + 1];
                    mma16816(c0, ah[mt][0], ah[mt][1], ah[mt][2], ah[mt][3], wh0, wh1);
                    mma16816(c1, ah[mt][0], ah[mt][1], ah[mt][2], ah[mt][3], wh2, wh3);
                    mma16816(c0, al[mt][0], al[mt][1], al[mt][2], al[mt][3], wh0, wh1);
                    mma16816(c1, al[mt][0], al[mt][1], al[mt][2], al[mt][3], wh2, wh3);
                    mma16816(c0, ah[mt][0], ah[mt][1], ah[mt][2], ah[mt][3], wl0, wl1);
                    mma16816(c1, ah[mt][0], ah[mt][1], ah[mt][2], ah[mt][3], wl2, wl3);
                }
            }
        }
    }
}

// ---------------------------------------------------------------------------
// QKV projection GEMM (fp16 inputs via cp.async DB mainloop) with FUSED
// RoPE + fp16 + head-major epilogue. blockIdx.z: 0=Q, 1=K, 2=V.
// ---------------------------------------------------------------------------
__global__ __launch_bounds__(256) void gemm_qkv(const __half* __restrict__ Ih,
                                                const __half* __restrict__ Wh,
                                                const float* __restrict__ b0,
                                                const float* __restrict__ b1,
                                                const float* __restrict__ b2,
                                                const int* __restrict__ qpos,
                                                const int* __restrict__ kpos,
                                                __half* __restrict__ Qh,
                                                __half* __restrict__ Kh,
                                                __half* __restrict__ Vh)
{
    int z = blockIdx.z;
    const __half* A   = Ih + (size_t)z * (TT * CC);
    const __half* W   = Wh + (size_t)z * (CC * CC);
    const float* bias = z == 0 ? b0 : (z == 1 ? b1 : b2);
    const int* pos    = z == 0 ? qpos : kpos;
    __half* dst       = z == 0 ? Qh : (z == 1 ? Kh : Vh);
    float mult        = z == 0 ? QMULT : 1.0f;

    extern __shared__ char smraw[];
    __half* sm = reinterpret_cast<__half*>(smraw);
    int tid = threadIdx.x, lane = tid & 31, warp = tid >> 5;
    int wm = warp & 3, wn = warp >> 2;
    int row0 = blockIdx.y * 128;
    int col0 = blockIdx.x * 64;

    float acc[2][4][4];
    gemm_mainloop_h16(A, W, sm, row0, col0, tid, lane, wm, wn, acc);

    const float LOG2_100 = 6.643856189774724f;
    int jj0 = (lane & 3) * 2;
    float inv0 = exp2f(-(float)jj0 * 0.125f * LOG2_100);
    float inv1 = exp2f(-(float)(jj0 + 1) * 0.125f * LOG2_100);

#pragma unroll
    for (int mt = 0; mt < 2; mt++) {
        int t0 = row0 + wm * 32 + mt * 16 + (lane >> 2);
#pragma unroll
        for (int p = 0; p < 2; p++) {
            int c0 = col0 + wn * 32 + p * 16;
            int hh = c0 / HD;
            int chunk = c0 % HD;
            int a = chunk / 16;

            float bx1a = bias[c0 + jj0],     bx1b = bias[c0 + jj0 + 1];
            float bx2a = bias[c0 + 8 + jj0], bx2b = bias[c0 + 8 + jj0 + 1];

#pragma unroll
            for (int rh = 0; rh < 2; rh++) {
                int t = t0 + rh * 8;
                float x1a = acc[mt][p * 2][rh * 2 + 0] + bx1a;
                float x1b = acc[mt][p * 2][rh * 2 + 1] + bx1b;
                float x2a = acc[mt][p * 2 + 1][rh * 2 + 0] + bx2a;
                float x2b = acc[mt][p * 2 + 1][rh * 2 + 1] + bx2b;

                if (z < 2) {
                    float pp = (float)pos[t * 3 + a];
                    float sa, ca, sb, cb;
                    sincosf(pp * inv0, &sa, &ca);
                    sincosf(pp * inv1, &sb, &cb);
                    float n1a = x1a * ca - x2a * sa;
                    float n2a = x2a * ca + x1a * sa;
                    float n1b = x1b * cb - x2b * sb;
                    float n2b = x2b * cb + x1b * sb;
                    x1a = n1a; x2a = n2a; x1b = n1b; x2b = n2b;
                }

                int bb = t / NN, nn = t % NN;
                __half* d = dst + ((size_t)(bb * HH + hh) * NN + nn) * HD + chunk + jj0;
                *(unsigned int*)d       = packh2(x1a * mult, x1b * mult);
                *(unsigned int*)(d + 8) = packh2(x2a * mult, x2b * mult);
            }
        }
    }
}

// ---------------------------------------------------------------------------
// Output projection GEMM (split-fp16; fp32 epilogue to d_out).
// ---------------------------------------------------------------------------
__global__ __launch_bounds__(256) void gemm_out(const float* __restrict__ A,
                                                const float* __restrict__ W,
                                                const float* __restrict__ bias,
                                                float* __restrict__ out)
{
    extern __shared__ char smraw[];
    GemmSmemFull* sm = reinterpret_cast<GemmSmemFull*>(smraw);
    int tid = threadIdx.x, lane = tid & 31, warp = tid >> 5;
    int wm = warp & 3, wn = warp >> 2;
    int row0 = blockIdx.y * 128;
    int col0 = blockIdx.x * 64;

    float acc[2][4][4];
    gemm_mainloop_split(A, W, sm, row0, col0, tid, lane, wm, wn, acc);

#pragma unroll
    for (int mt = 0; mt < 2; mt++) {
        int r = row0 + wm * 32 + mt * 16 + (lane >> 2);
#pragma unroll
        for (int n8 = 0; n8 < 4; n8++) {
            int c = col0 + wn * 32 + n8 * 8 + (lane & 3) * 2;
            float bx = bias[c], by = bias[c + 1];
            float2 f0, f1;
            f0.x = acc[mt][n8][0] + bx; f0.y = acc[mt][n8][1] + by;
            f1.x = acc[mt][n8][2] + bx; f1.y = acc[mt][n8][3] + by;
            *(float2*)&out[(size_t)r * CC + c] = f0;
            *(float2*)&out[(size_t)(r + 8) * CC + c] = f1;
        }
    }
}

// ---------------------------------------------------------------------------
// Tensor-core flash attention (R15 configuration — validated at 168 us).
// 128 queries, 4 warps (warp = 32 rows, two m16 fragments); 64-key tiles
// double-buffered via cp.async; exp2-domain softmax with ex2.approx.f16x2;
// tensor-core denominator via ones-column; per-row max frozen after tile 0.
// ---------------------------------------------------------------------------
#define ATS 56
#define QT 128

__global__ __launch_bounds__(128) void attn_mma(const __half* __restrict__ Qh,
                                                const __half* __restrict__ Kh,
                                                const __half* __restrict__ Vh,
                                                float* __restrict__ X)
{
    __shared__ __half Qs[QT * ATS];
    __shared__ __half Ks[2][64 * ATS];
    __shared__ __half Vs[2][64 * ATS];

    int tid = threadIdx.x, lane = tid & 31, w = tid >> 5;
    int b = blockIdx.z, h = blockIdx.y;
    const size_t hb = ((size_t)(b * HH + h)) * NN * HD;
    int q0 = blockIdx.x * QT;

    unsigned int qs_base = (unsigned int)__cvta_generic_to_shared(Qs);
    unsigned int ks_base = (unsigned int)__cvta_generic_to_shared(&Ks[0][0]);
    unsigned int vs_base = (unsigned int)__cvta_generic_to_shared(&Vs[0][0]);
    const unsigned int BUFB = 64 * ATS * 2;

    if (tid < 64) {
        uint4 ones = {0x00003C00u, 0u, 0u, 0u};
        *(uint4*)&Vs[0][tid * ATS + 48] = ones;
        *(uint4*)&Vs[1][tid * ATS + 48] = ones;
    }

    for (int e = tid; e < QT * 6; e += 128) {
        int r = e / 6, c = e % 6;
        *(uint4*)&Qs[r * ATS + c * 8] = *(const uint4*)(Qh + hb + (size_t)(q0 + r) * HD + c * 8);
    }

    size_t gofs[3];
    unsigned int sofs[3];
#pragma unroll
    for (int p = 0; p < 3; p++) {
        int e = tid + p * 128;
        int r = e / 6, c = e % 6;
        gofs[p] = (size_t)r * HD + c * 8;
        sofs[p] = (unsigned int)((r * ATS + c * 8) * 2);
    }

#pragma unroll
    for (int p = 0; p < 3; p++) {
        cp16(ks_base + sofs[p], Kh + hb + gofs[p]);
        cp16(vs_base + sofs[p], Vh + hb + gofs[p]);
    }
    CP_COMMIT();
    __syncthreads();

    unsigned int qa[2][3][4];
#pragma unroll
    for (int mt = 0; mt < 2; mt++) {
        int arow = w * 32 + mt * 16 + (lane & 15);
        int acol = (lane >> 4) * 8;
#pragma unroll
        for (int k = 0; k < 3; k++) {
            unsigned int addr = qs_base + (unsigned int)((arow * ATS + k * 16 + acol) * 2);
            ldsm_x4(addr, qa[mt][k][0], qa[mt][k][1], qa[mt][k][2], qa[mt][k][3]);
        }
    }

    float o[2][6][4];
    float ol[2][4];
    float m[2][2];
#pragma unroll
    for (int mt = 0; mt < 2; mt++) {
#pragma unroll
        for (int j = 0; j < 4; j++) ol[mt][j] = 0.f;
#pragma unroll
        for (int n = 0; n < 6; n++)
#pragma unroll
            for (int j = 0; j < 4; j++) o[mt][n][j] = 0.f;
    }

    int kb_off = ((lane & 7) + ((lane >> 4) & 1) * 8) * ATS + ((lane >> 3) & 1) * 8;
    int vb_off = ((lane & 7) + ((lane >> 3) & 1) * 8) * ATS + ((lane >> 4) & 1) * 8;
    int vl_off = (lane & 15) * ATS + 48;

    const int NT = NN / 64;
    for (int kt = 0; kt < NT; kt++) {
        if (kt + 1 < NT) {
            unsigned int bo = ((kt + 1) & 1) * BUFB;
            size_t gb = hb + (size_t)(kt + 1) * 64 * HD;
#pragma unroll
            for (int p = 0; p < 3; p++) {
                cp16(ks_base + bo + sofs[p], Kh + gb + gofs[p]);
                cp16(vs_base + bo + sofs[p], Vh + gb + gofs[p]);
            }
            CP_COMMIT();
            CP_WAIT(1);
        } else {
            CP_WAIT(0);
        }
        __syncthreads();

        unsigned int bo = (kt & 1) * BUFB;

        float s[2][8][4];
#pragma unroll
        for (int mt = 0; mt < 2; mt++)
#pragma unroll
            for (int n = 0; n < 8; n++)
#pragma unroll
                for (int j = 0; j < 4; j++) s[mt][n][j] = 0.f;

#pragma unroll
        for (int np = 0; np < 4; np++) {
#pragma unroll
            for (int k = 0; k < 3; k++) {
                unsigned int addr = ks_base + bo +
                    (unsigned int)(((np * 16) * ATS + k * 16 + kb_off) * 2);
                unsigned int b0, b1, b2, b3;
                ldsm_x4(addr, b0, b1, b2, b3);
#pragma unroll
                for (int mt = 0; mt < 2; mt++) {
                    mma16816(s[mt][2 * np],     qa[mt][k][0], qa[mt][k][1], qa[mt][k][2], qa[mt][k][3], b0, b1);
                    mma16816(s[mt][2 * np + 1], qa[mt][k][0], qa[mt][k][1], qa[mt][k][2], qa[mt][k][3], b2, b3);
                }
            }
        }

        if (kt == 0) {
#pragma unroll
            for (int mt = 0; mt < 2; mt++) {
                float t0 = s[mt][0][0], t1 = s[mt][0][2];
#pragma unroll
                for (int n = 0; n < 8; n++) {
                    t0 = fmaxf(t0, fmaxf(s[mt][n][0], s[mt][n][1]));
                    t1 = fmaxf(t1, fmaxf(s[mt][n][2], s[mt][n][3]));
                }
                t0 = fmaxf(t0, __shfl_xor_sync(0xffffffffu, t0, 1));
                t0 = fmaxf(t0, __shfl_xor_sync(0xffffffffu, t0, 2));
                t1 = fmaxf(t1, __shfl_xor_sync(0xffffffffu, t1, 1));
                t1 = fmaxf(t1, __shfl_xor_sync(0xffffffffu, t1, 2));
                m[mt][0] = t0; m[mt][1] = t1;
            }
        }

#pragma unroll
        for (int k4 = 0; k4 < 4; k4++) {
            unsigned int a[2][4];
#pragma unroll
            for (int mt = 0; mt < 2; mt++) {
                float m0 = m[mt][0], m1 = m[mt][1];
                a[mt][0] = h2ex2(packh2(s[mt][2 * k4][0] - m0,     s[mt][2 * k4][1] - m0));
                a[mt][1] = h2ex2(packh2(s[mt][2 * k4][2] - m1,     s[mt][2 * k4][3] - m1));
                a[mt][2] = h2ex2(packh2(s[mt][2 * k4 + 1][0] - m0, s[mt][2 * k4 + 1][1] - m0));
                a[mt][3] = h2ex2(packh2(s[mt][2 * k4 + 1][2] - m1, s[mt][2 * k4 + 1][3] - m1));
            }
#pragma unroll
            for (int np = 0; np < 3; np++) {
                unsigned int addr = vs_base + bo +
                    (unsigned int)(((k4 * 16) * ATS + np * 16 + vb_off) * 2);
                unsigned int b0, b1, b2, b3;
                ldsm_x4_t(addr, b0, b1, b2, b3);
#pragma unroll
                for (int mt = 0; mt < 2; mt++) {
                    mma16816(o[mt][2 * np],     a[mt][0], a[mt][1], a[mt][2], a[mt][3], b0, b1);
                    mma16816(o[mt][2 * np + 1], a[mt][0], a[mt][1], a[mt][2], a[mt][3], b2, b3);
                }
            }
            {
                unsigned int laddr = vs_base + bo +
                    (unsigned int)(((k4 * 16) * ATS + vl_off) * 2);
                unsigned int b0, b1;
                ldsm_x2_t(laddr, b0, b1);
#pragma unroll
                for (int mt = 0; mt < 2; mt++)
                    mma16816(ol[mt], a[mt][0], a[mt][1], a[mt][2], a[mt][3], b0, b1);
            }
        }
        __syncthreads();
    }

#pragma unroll
    for (int mt = 0; mt < 2; mt++) {
        float l0 = __shfl_sync(0xffffffffu, ol[mt][0], lane & ~3);
        float l1 = __shfl_sync(0xffffffffu, ol[mt][2], lane & ~3);
        float i0 = 1.f / l0, i1 = 1.f / l1;

        int r0 = q0 + w * 32 + mt * 16 + (lane >> 2);
        int cbase = h * HD + (lane & 3) * 2;
#pragma unroll
        for (int n = 0; n < 6; n++) {
            float2 f0; f0.x = o[mt][n][0] * i0; f0.y = o[mt][n][1] * i0;
            float2 f1; f1.x = o[mt][n][2] * i1; f1.y = o[mt][n][3] * i1;
            *(float2*)&X[(size_t)(b * NN + r0) * CC + cbase + n * 8] = f0;
            *(float2*)&X[(size_t)(b * NN + r0 + 8) * CC + cbase + n * 8] = f1;
        }
    }
}

// ---------------------------------------------------------------------------
// Launch
// ---------------------------------------------------------------------------
extern "C" void kernel_launch(void* const* d_in, const int* in_sizes, int n_in,
                              void* d_out, int out_size)
{
    const float* query = (const float*)d_in[0];
    const float* key   = (const float*)d_in[1];
    const float* value = (const float*)d_in[2];
    const float* Wq = (const float*)d_in[3];
    const float* bq = (const float*)d_in[4];
    const float* Wk = (const float*)d_in[5];
    const float* bk = (const float*)d_in[6];
    const float* Wv = (const float*)d_in[7];
    const float* bv = (const float*)d_in[8];
    const float* Wo = (const float*)d_in[9];
    const float* bo = (const float*)d_in[10];
    const int* qpos = (const int*)d_in[11];
    const int* kpos = (const int*)d_in[12];
    float* out = (float*)d_out;

    float* pX;
    __half *pQh, *pKh, *pVh, *pIh, *pWh;
    cudaGetSymbolAddress((void**)&pX, g_X);
    cudaGetSymbolAddress((void**)&pQh, g_Qh);
    cudaGetSymbolAddress((void**)&pKh, g_Kh);
    cudaGetSymbolAddress((void**)&pVh, g_Vh);
    cudaGetSymbolAddress((void**)&pIh, g_Ih);
    cudaGetSymbolAddress((void**)&pWh, g_Wh);

    // fp32 -> fp16 pre-conversion of QKV inputs + weights (one launch)
    const int n_cvt = 3 * (TT * CC / 8) + 3 * (CC * CC / 8);   // 1234944
    cvt_in<<<(n_cvt + 255) / 256, 256>>>(query, key, value, Wq, Wk, Wv, pIh, pWh);

    const int smem_db   = 2 * BUFE * 2;                // 30720 B (cp.async DB fp16)
    const int smem_full = 2 * (128 + 64) * GS * 2;     // 30720 B (split, single-buffered)

    dim3 g3(CC / 64, TT / 128, 3);
    gemm_qkv<<<g3, 256, smem_db>>>(pIh, pWh,
                                   bq, bk, bv,
                                   qpos, kpos,
                                   pQh, pKh, pVh);

    attn_mma<<<dim3(NN / QT, HH, BB), 128>>>(pQh, pKh, pVh, pX);

    dim3 g1(CC / 64, TT / 128);
    gemm_out<<<g1, 256, smem_full>>>(pX, Wo, bo, out);
}